// round 14
// baseline (speedup 1.0000x reference)
#include <cuda_runtime.h>
#include <cuda_fp16.h>
#include <cstdint>

#define HID   4096
#define NH    32
#define NKV   8
#define HD    128
#define BATCH 4
#define SEQ   1024
#define MROWS (BATCH*SEQ)   // 4096

// ---------------------------------------------------------------------------
// Scratch (static __device__ — no allocations allowed)
// ---------------------------------------------------------------------------
__device__ __half g_qh [(size_t)BATCH*NH *SEQ*HD];  // (b,h,t,d) fp16
__device__ __half g_kh [(size_t)BATCH*NKV*SEQ*HD];  // (b,kvh,t,d)
__device__ __half g_vh [(size_t)BATCH*NKV*SEQ*HD];
__device__ __half g_oh [(size_t)MROWS*HID];         // attention out fp16
__device__ __half g_hh [(size_t)MROWS*HID];         // hidden fp16
__device__ __half g_wqh[(size_t)HID*HID];
__device__ __half g_wkh[(size_t)NKV*HD*HID];
__device__ __half g_wvh[(size_t)NKV*HD*HID];
__device__ __half g_woh[(size_t)HID*HID];

// ---------------------------------------------------------------------------
__device__ __forceinline__ uint32_t h2_as_u32(__half2 h) {
    uint32_t u; memcpy(&u, &h, 4); return u;
}
__device__ __forceinline__ void cpasync16s(uint32_t s, const void* g) {
    asm volatile("cp.async.cg.shared.global [%0], [%1], 16;" :: "r"(s), "l"(g));
}
#define CP_COMMIT() asm volatile("cp.async.commit_group;")
#define CP_WAIT(n)  asm volatile("cp.async.wait_group %0;" :: "n"(n))

#define LDMX4(r0,r1,r2,r3, addr) \
    asm volatile("ldmatrix.sync.aligned.m8n8.x4.shared.b16 {%0,%1,%2,%3}, [%4];" \
        : "=r"(r0), "=r"(r1), "=r"(r2), "=r"(r3) : "r"(addr))

#define LDMX4T(r0,r1,r2,r3, addr) \
    asm volatile("ldmatrix.sync.aligned.m8n8.x4.trans.shared.b16 {%0,%1,%2,%3}, [%4];" \
        : "=r"(r0), "=r"(r1), "=r"(r2), "=r"(r3) : "r"(addr))

#define MMA16(d, a, b0, b1) \
    asm volatile("mma.sync.aligned.m16n8k16.row.col.f32.f16.f16.f32 " \
        "{%0,%1,%2,%3}, {%4,%5,%6,%7}, {%8,%9}, {%0,%1,%2,%3};" \
        : "+f"((d)[0]), "+f"((d)[1]), "+f"((d)[2]), "+f"((d)[3]) \
        : "r"((a)[0]), "r"((a)[1]), "r"((a)[2]), "r"((a)[3]), "r"(b0), "r"(b1))

// ---------------------------------------------------------------------------
// FP16 mma.sync GEMM:  C = A[M,K] * B[N,K]^T.
// 256x128 CTA tile, BK=64 (128B rows, XOR swizzle c^(r&7)), 3-stage cp.async
// (144KB, 1 CTA/SM), 8 warps in 4x2 -> warp tile 64x64, m16n8k16.
// MMA:LDSM = 128:32 per warp-iteration (2x better than 64x32 tiles).
// MODE 0: f32 C[m*N+n]; MODE 1: fp16 scatter (b,h,t,d) 32 heads; MODE 2: 8.
// ---------------------------------------------------------------------------
#define A_STAGE 32768                    // 256 rows * 128B
#define B_STAGE 16384                    // 128 rows * 128B
#define GEMM_SMEM (3*(A_STAGE + B_STAGE))   // 147456

template<int MODE>
__global__ __launch_bounds__(256, 1)
void gemm_f16(const __half* __restrict__ A, const __half* __restrict__ Bw,
              void* __restrict__ Cv, int N, int K)
{
    extern __shared__ __align__(128) uint8_t sm[];
    const uint32_t sbase = (uint32_t)__cvta_generic_to_shared(sm);
    const uint32_t aB0 = sbase;
    const uint32_t bB0 = sbase + 3*A_STAGE;

    const int tid  = threadIdx.x;
    const int w    = tid >> 5;
    const int lane = tid & 31;
    const int wm   = (w & 3) * 64;       // 4 warps along M
    const int wn   = (w >> 2) * 64;      // 2 warps along N
    const int mBase = blockIdx.y << 8;   // 256-row tiles
    const int nBase = blockIdx.x << 7;   // 128-col tiles
    const __half* Ag = A  + (size_t)mBase * K;
    const __half* Bg = Bw + (size_t)nBase * K;

    // ldmatrix lane geometry (128B rows, swizzle idx = row & 7)
    const int ar  = wm + ((lane >> 3) & 1) * 8 + (lane & 7);
    const int ahi = lane >> 4;
    const int br  = wn + ((lane >> 4) & 1) * 8 + (lane & 7);
    const int bhi = (lane >> 3) & 1;
    const int asw = ar & 7;
    const int bsw = br & 7;

    float acc[4][8][4];
#pragma unroll
    for (int i = 0; i < 4; i++)
#pragma unroll
        for (int j = 0; j < 8; j++)
#pragma unroll
            for (int r = 0; r < 4; r++) acc[i][j][r] = 0.f;

    // cp.async: A 2048 chunks (8/thread), B 1024 chunks (4/thread)
    auto issue = [&](int kt) {
        const int st = kt - (kt/3)*3;
        const int k0 = kt << 6;
        const uint32_t aS = aB0 + st*A_STAGE;
        const uint32_t bS = bB0 + st*B_STAGE;
#pragma unroll
        for (int i = 0; i < 8; i++) {
            int slot = tid + (i << 8);
            int r = slot >> 3;           // row 0..255
            int c = slot & 7;
            uint32_t dst = (uint32_t)(r*128 + ((c ^ (r & 7)) << 4));
            cpasync16s(aS + dst, Ag + (size_t)r * K + k0 + c*8);
        }
#pragma unroll
        for (int i = 0; i < 4; i++) {
            int slot = tid + (i << 8);
            int r = slot >> 3;           // row 0..127
            int c = slot & 7;
            uint32_t dst = (uint32_t)(r*128 + ((c ^ (r & 7)) << 4));
            cpasync16s(bS + dst, Bg + (size_t)r * K + k0 + c*8);
        }
    };

    const int kTiles = K >> 6;           // K/64
    issue(0); CP_COMMIT();
    issue(1); CP_COMMIT();

    for (int kt = 0; kt < kTiles; kt++) {
        CP_WAIT(1);
        __syncthreads();
        if (kt + 2 < kTiles) issue(kt + 2);
        CP_COMMIT();

        const int st = kt - (kt/3)*3;
        const uint32_t aS = aB0 + st*A_STAGE;
        const uint32_t bS = bB0 + st*B_STAGE;

#pragma unroll
        for (int h = 0; h < 4; h++) {
            uint32_t a[4][4], b[4][4];
#pragma unroll
            for (int mt = 0; mt < 4; mt++) {
                uint32_t ad = aS + (uint32_t)((ar + mt*16)*128
                              + (((2*h + ahi) ^ asw) << 4));
                LDMX4(a[mt][0], a[mt][1], a[mt][2], a[mt][3], ad);
            }
#pragma unroll
            for (int p = 0; p < 4; p++) {
                uint32_t bd = bS + (uint32_t)((br + p*16)*128
                              + (((2*h + bhi) ^ bsw) << 4));
                LDMX4(b[p][0], b[p][1], b[p][2], b[p][3], bd);
            }
#pragma unroll
            for (int mt = 0; mt < 4; mt++)
#pragma unroll
                for (int p = 0; p < 4; p++) {
                    MMA16(acc[mt][2*p],     a[mt], b[p][0], b[p][1]);
                    MMA16(acc[mt][2*p + 1], a[mt], b[p][2], b[p][3]);
                }
        }
    }

    const int g = lane >> 2, t = lane & 3;
#pragma unroll
    for (int mt = 0; mt < 4; mt++) {
#pragma unroll
        for (int nt = 0; nt < 8; nt++) {
            int m = mBase + wm + mt*16 + g;
            int n = nBase + wn + nt*8 + 2*t;
#pragma unroll
            for (int half = 0; half < 2; half++) {
                int mm = m + half*8;
                float v0 = half ? acc[mt][nt][2] : acc[mt][nt][0];
                float v1 = half ? acc[mt][nt][3] : acc[mt][nt][1];
                if (MODE == 0) {
                    float* C = (float*)Cv;
                    *(float2*)&C[(size_t)mm * N + n] = make_float2(v0, v1);
                } else {
                    __half* C = (__half*)Cv;
                    int bb = mm >> 10, tk = mm & 1023;
                    int h2 = n >> 7, d = n & 127;
                    int heads = (MODE == 1) ? NH : NKV;
                    __half2 hv = __floats2half2_rn(v0, v1);
                    *(uint32_t*)&C[(((size_t)(bb*heads + h2))*SEQ + tk)*HD + d] = h2_as_u32(hv);
                }
            }
        }
    }
}

// ---------------------------------------------------------------------------
// f32 -> fp16 conversion pre-pass
// ---------------------------------------------------------------------------
__global__ void to_half_kernel(__half* __restrict__ dst, const float* __restrict__ src, int n8)
{
    int i = blockIdx.x * blockDim.x + threadIdx.x;
    if (i < n8) {
        float4 v0 = ((const float4*)src)[2*i];
        float4 v1 = ((const float4*)src)[2*i + 1];
        uint4 o;
        o.x = h2_as_u32(__floats2half2_rn(v0.x, v0.y));
        o.y = h2_as_u32(__floats2half2_rn(v0.z, v0.w));
        o.z = h2_as_u32(__floats2half2_rn(v1.x, v1.y));
        o.w = h2_as_u32(__floats2half2_rn(v1.z, v1.w));
        ((uint4*)dst)[i] = o;
    }
}

// ---------------------------------------------------------------------------
// Tensor-core flash attention (fp16 in, f32 softmax/accum, fp16 out).
// Block: 128 q-rows of one (b,h); 8 warps, 16 rows each. K/V tiles of 64
// keys, 3-stage cp.async. Mask: kpos <= qpos+1 AND id[kpos]!=0; kvh = h%8.
// ---------------------------------------------------------------------------
#define ATTN_SMEM (32768 + 3*16384 + 3*16384 + 256)

__global__ __launch_bounds__(256, 1)
void attn_f16(const int* __restrict__ ids)
{
    extern __shared__ __align__(128) uint8_t smraw[];
    const uint32_t sb = (uint32_t)__cvta_generic_to_shared(smraw);
    const uint32_t Qs = sb;
    const uint32_t Ks = sb + 32768;
    const uint32_t Vs = sb + 32768 + 3*16384;
    float* padb = (float*)(smraw + 32768 + 6*16384);

    const int qt = blockIdx.x, h = blockIdx.y, b = blockIdx.z;
    const int qb  = qt << 7;
    const int kvh = h & 7;
    const int tid = threadIdx.x, w = tid >> 5, lane = tid & 31;
    const int g = lane >> 2, t4 = lane & 3;

    const __half* Qg = g_qh + ((size_t)((b*NH  + h  )*SEQ) + qb) * HD;
    const __half* Kg = g_kh + ((size_t)((b*NKV + kvh)*SEQ)) * HD;
    const __half* Vg = g_vh + ((size_t)((b*NKV + kvh)*SEQ)) * HD;

#pragma unroll
    for (int i = 0; i < 8; i++) {
        int slot = tid + (i << 8);
        int r = slot >> 4, c = slot & 15;
        cpasync16s(Qs + r*256 + ((c ^ (r & 7)) << 4), Qg + (size_t)r*HD + c*8);
    }
    CP_COMMIT();

    const int limit = min(SEQ, qb + 129);
    const int nT = (limit + 63) >> 6;

    auto issueKV = [&](int tt) {
        int st = tt % 3; int k0 = tt << 6;
#pragma unroll
        for (int i = 0; i < 4; i++) {
            int slot = tid + (i << 8);
            int r = slot >> 4, c = slot & 15;
            uint32_t off = (uint32_t)(r*256 + ((c ^ (r & 7)) << 4));
            cpasync16s(Ks + st*16384 + off, Kg + (size_t)(k0 + r)*HD + c*8);
            cpasync16s(Vs + st*16384 + off, Vg + (size_t)(k0 + r)*HD + c*8);
        }
    };

    issueKV(0); CP_COMMIT();
    if (nT > 1) issueKV(1);
    CP_COMMIT();

    CP_WAIT(2);
    __syncthreads();

    uint32_t qf[8][4];
    const int arow = (w << 4) + (lane & 7) + (((lane >> 3) & 1) << 3);
    const int ahi  = lane >> 4;
#pragma unroll
    for (int kt = 0; kt < 8; kt++) {
        int c = kt*2 + ahi;
        uint32_t ad = Qs + (uint32_t)(arow*256 + ((c ^ (arow & 7)) << 4));
        LDMX4(qf[kt][0], qf[kt][1], qf[kt][2], qf[kt][3], ad);
    }

    const int krow = (lane & 7) + (((lane >> 4) & 1) << 3);
    const int khi  = (lane >> 3) & 1;
    const int vkey = lane & 15;
    const int vhi  = lane >> 4;
    const int row0 = qb + (w << 4) + g;
    const int row1 = row0 + 8;
    const int minrow = qb + (w << 4);

    float m0 = -1e30f, m1 = -1e30f, l0 = 0.f, l1 = 0.f;
    float oacc[16][4];
#pragma unroll
    for (int i = 0; i < 16; i++)
#pragma unroll
        for (int j = 0; j < 4; j++) oacc[i][j] = 0.f;

    for (int tt = 0; tt < nT; tt++) {
        const int st = tt % 3;
        const int k0 = tt << 6;

        __syncthreads();
        if (tid < 64) padb[tid] = (ids[b*SEQ + k0 + tid] != 0) ? 0.f : -1e30f;
        if (tt + 2 < nT) issueKV(tt + 2);
        CP_COMMIT();
        CP_WAIT(2);
        __syncthreads();

        float sacc[8][4];
#pragma unroll
        for (int nt = 0; nt < 8; nt++)
#pragma unroll
            for (int j = 0; j < 4; j++) sacc[nt][j] = 0.f;

        const uint32_t KsS = Ks + st*16384;
#pragma unroll
        for (int np = 0; np < 4; np++) {
#pragma unroll
            for (int kt = 0; kt < 8; kt++) {
                int r = np*16 + krow;
                int c = kt*2 + khi;
                uint32_t bd = KsS + (uint32_t)(r*256 + ((c ^ (r & 7)) << 4));
                uint32_t b0, b1, b2, b3;
                LDMX4(b0, b1, b2, b3, bd);
                MMA16(sacc[np*2],     qf[kt], b0, b1);
                MMA16(sacc[np*2 + 1], qf[kt], b2, b3);
            }
        }

        const bool fullc = (k0 + 63 <= minrow + 1);
        const float sc = 0.08838834764831845f;
        float mx0 = -1e30f, mx1 = -1e30f;
        const float2* pb2 = (const float2*)padb;
#pragma unroll
        for (int nt = 0; nt < 8; nt++) {
            float2 pb = pb2[nt*4 + t4];
            float c0 = sacc[nt][0]*sc + pb.x;
            float c1 = sacc[nt][1]*sc + pb.y;
            float c2 = sacc[nt][2]*sc + pb.x;
            float c3 = sacc[nt][3]*sc + pb.y;
            if (!fullc) {
                int col0 = k0 + nt*8 + 2*t4;
                if (col0     > row0 + 1) c0 = -1e30f;
                if (col0 + 1 > row0 + 1) c1 = -1e30f;
                if (col0     > row1 + 1) c2 = -1e30f;
                if (col0 + 1 > row1 + 1) c3 = -1e30f;
            }
            sacc[nt][0] = c0; sacc[nt][1] = c1; sacc[nt][2] = c2; sacc[nt][3] = c3;
            mx0 = fmaxf(mx0, fmaxf(c0, c1));
            mx1 = fmaxf(mx1, fmaxf(c2, c3));
        }
        mx0 = fmaxf(mx0, __shfl_xor_sync(0xffffffffu, mx0, 1));
        mx0 = fmaxf(mx0, __shfl_xor_sync(0xffffffffu, mx0, 2));
        mx1 = fmaxf(mx1, __shfl_xor_sync(0xffffffffu, mx1, 1));
        mx1 = fmaxf(mx1, __shfl_xor_sync(0xffffffffu, mx1, 2));
        float mn0 = fmaxf(m0, mx0), mn1 = fmaxf(m1, mx1);
        float f0 = __expf(m0 - mn0), f1 = __expf(m1 - mn1);
        m0 = mn0; m1 = mn1;

        float s0 = 0.f, s1 = 0.f;
        uint32_t ph[8][2];
#pragma unroll
        for (int nt = 0; nt < 8; nt++) {
            float p0 = __expf(sacc[nt][0] - mn0);
            float p1 = __expf(sacc[nt][1] - mn0);
            float p2 = __expf(sacc[nt][2] - mn1);
            float p3 = __expf(sacc[nt][3] - mn1);
            s0 += p0 + p1; s1 += p2 + p3;
            ph[nt][0] = h2_as_u32(__floats2half2_rn(p0, p1));
            ph[nt][1] = h2_as_u32(__floats2half2_rn(p2, p3));
        }
        s0 += __shfl_xor_sync(0xffffffffu, s0, 1);
        s0 += __shfl_xor_sync(0xffffffffu, s0, 2);
        s1 += __shfl_xor_sync(0xffffffffu, s1, 1);
        s1 += __shfl_xor_sync(0xffffffffu, s1, 2);
        l0 = l0*f0 + s0; l1 = l1*f1 + s1;

#pragma unroll
        for (int nt = 0; nt < 16; nt++) {
            oacc[nt][0] *= f0; oacc[nt][1] *= f0;
            oacc[nt][2] *= f1; oacc[nt][3] *= f1;
        }

        const uint32_t VsS = Vs + st*16384;
#pragma unroll
        for (int kt2 = 0; kt2 < 4; kt2++) {
            uint32_t a[4] = { ph[kt2*2][0], ph[kt2*2][1],
                              ph[kt2*2 + 1][0], ph[kt2*2 + 1][1] };
#pragma unroll
            for (int u = 0; u < 8; u++) {
                int key = kt2*16 + vkey;
                int c = u*2 + vhi;
                uint32_t vd = VsS + (uint32_t)(key*256 + ((c ^ (key & 7)) << 4));
                uint32_t r0, r1, r2, r3;
                LDMX4T(r0, r1, r2, r3, vd);
                MMA16(oacc[u*2],     a, r0, r1);
                MMA16(oacc[u*2 + 1], a, r2, r3);
            }
        }
    }

    float i0 = 1.f / l0, i1 = 1.f / l1;
    size_t base0 = ((size_t)b*SEQ + row0)*HID + h*HD;
    size_t base1 = ((size_t)b*SEQ + row1)*HID + h*HD;
#pragma unroll
    for (int nt = 0; nt < 16; nt++) {
        int d = nt*8 + 2*t4;
        __half2 v0 = __floats2half2_rn(oacc[nt][0]*i0, oacc[nt][1]*i0);
        __half2 v1 = __floats2half2_rn(oacc[nt][2]*i1, oacc[nt][3]*i1);
        *(uint32_t*)(g_oh + base0 + d) = h2_as_u32(v0);
        *(uint32_t*)(g_oh + base1 + d) = h2_as_u32(v1);
    }
}

// Tail: reference returns (out, start_pos + Tq) — fill any extra output slots.
__global__ void tail_kernel(float* __restrict__ out, const int* __restrict__ sp, int out_size)
{
    int i = MROWS*HID + blockIdx.x*blockDim.x + threadIdx.x;
    if (i < out_size) {
        int s = sp ? *sp : 0;
        out[i] = (float)(s + SEQ);
    }
}

// ---------------------------------------------------------------------------
extern "C" void kernel_launch(void* const* d_in, const int* in_sizes, int n_in,
                              void* d_out, int out_size)
{
    const int*   ids    = (const int*)  d_in[0];
    const float* hidden = (const float*)d_in[1];
    const float* Wq     = (const float*)d_in[2];
    const float* Wk     = (const float*)d_in[3];
    const float* Wv     = (const float*)d_in[4];
    const float* Wo     = (const float*)d_in[5];
    float*       out    = (float*)d_out;

    __half *qh, *kh, *vh, *oh, *hh, *wqh, *wkh, *wvh, *woh;
    cudaGetSymbolAddress((void**)&qh,  g_qh);
    cudaGetSymbolAddress((void**)&kh,  g_kh);
    cudaGetSymbolAddress((void**)&vh,  g_vh);
    cudaGetSymbolAddress((void**)&oh,  g_oh);
    cudaGetSymbolAddress((void**)&hh,  g_hh);
    cudaGetSymbolAddress((void**)&wqh, g_wqh);
    cudaGetSymbolAddress((void**)&wkh, g_wkh);
    cudaGetSymbolAddress((void**)&wvh, g_wvh);
    cudaGetSymbolAddress((void**)&woh, g_woh);

    cudaFuncSetAttribute(gemm_f16<0>, cudaFuncAttributeMaxDynamicSharedMemorySize, GEMM_SMEM);
    cudaFuncSetAttribute(gemm_f16<1>, cudaFuncAttributeMaxDynamicSharedMemorySize, GEMM_SMEM);
    cudaFuncSetAttribute(gemm_f16<2>, cudaFuncAttributeMaxDynamicSharedMemorySize, GEMM_SMEM);
    cudaFuncSetAttribute(attn_f16,    cudaFuncAttributeMaxDynamicSharedMemorySize, ATTN_SMEM);

    auto conv = [&](__half* d, const float* s, size_t n) {
        int n8 = (int)(n / 8);
        to_half_kernel<<<(n8 + 255)/256, 256>>>(d, s, n8);
    };

    dim3 blk(256);
    conv(hh,  hidden, (size_t)MROWS*HID);                                     // 1
    conv(wqh, Wq,     (size_t)HID*HID);                                       // 2
    conv(wkh, Wk,     (size_t)NKV*HD*HID);                                    // 3
    gemm_f16<1><<<dim3(HID/128,      MROWS/256), blk, GEMM_SMEM>>>(hh, wqh, qh, HID,    HID); // 4 <- profiled
    conv(wvh, Wv,     (size_t)NKV*HD*HID);                                    // 5
    conv(woh, Wo,     (size_t)HID*HID);                                       // 6
    gemm_f16<2><<<dim3((NKV*HD)/128, MROWS/256), blk, GEMM_SMEM>>>(hh, wkh, kh, NKV*HD, HID); // 7
    gemm_f16<2><<<dim3((NKV*HD)/128, MROWS/256), blk, GEMM_SMEM>>>(hh, wvh, vh, NKV*HD, HID); // 8

    attn_f16<<<dim3(SEQ/128, NH, BATCH), blk, ATTN_SMEM>>>(ids);              // 9

    gemm_f16<0><<<dim3(HID/128, MROWS/256), blk, GEMM_SMEM>>>(oh, woh, out, HID, HID); // 10

    if (out_size > MROWS*HID) {
        int rem = out_size - MROWS*HID;
        const int* sp = (n_in > 8) ? (const int*)d_in[8] : nullptr;
        tail_kernel<<<(rem + 127)/128, 128>>>(out, sp, out_size);             // 11
    }
}

// round 15
// speedup vs baseline: 1.0624x; 1.0624x over previous
#include <cuda_runtime.h>
#include <cuda_fp16.h>
#include <cstdint>

#define HID   4096
#define NH    32
#define NKV   8
#define HD    128
#define BATCH 4
#define SEQ   1024
#define MROWS (BATCH*SEQ)   // 4096

// ---------------------------------------------------------------------------
// Scratch (static __device__ — no allocations allowed)
// ---------------------------------------------------------------------------
__device__ __half g_qh [(size_t)BATCH*NH *SEQ*HD];  // (b,h,t,d) fp16
__device__ __half g_kh [(size_t)BATCH*NKV*SEQ*HD];  // (b,kvh,t,d)
__device__ __half g_vh [(size_t)BATCH*NKV*SEQ*HD];
__device__ __half g_oh [(size_t)MROWS*HID];         // attention out fp16
__device__ __half g_hh [(size_t)MROWS*HID];         // hidden fp16
__device__ __half g_wqh[(size_t)HID*HID];
__device__ __half g_wkh[(size_t)NKV*HD*HID];
__device__ __half g_wvh[(size_t)NKV*HD*HID];
__device__ __half g_woh[(size_t)HID*HID];

// ---------------------------------------------------------------------------
__device__ __forceinline__ uint32_t h2_as_u32(__half2 h) {
    uint32_t u; memcpy(&u, &h, 4); return u;
}
__device__ __forceinline__ void cpasync16s(uint32_t s, const void* g) {
    asm volatile("cp.async.cg.shared.global [%0], [%1], 16;" :: "r"(s), "l"(g));
}
#define CP_COMMIT() asm volatile("cp.async.commit_group;")
#define CP_WAIT(n)  asm volatile("cp.async.wait_group %0;" :: "n"(n))

#define LDMX4(r0,r1,r2,r3, addr) \
    asm volatile("ldmatrix.sync.aligned.m8n8.x4.shared.b16 {%0,%1,%2,%3}, [%4];" \
        : "=r"(r0), "=r"(r1), "=r"(r2), "=r"(r3) : "r"(addr))

#define LDMX4T(r0,r1,r2,r3, addr) \
    asm volatile("ldmatrix.sync.aligned.m8n8.x4.trans.shared.b16 {%0,%1,%2,%3}, [%4];" \
        : "=r"(r0), "=r"(r1), "=r"(r2), "=r"(r3) : "r"(addr))

#define MMA16(d, a, b0, b1) \
    asm volatile("mma.sync.aligned.m16n8k16.row.col.f32.f16.f16.f32 " \
        "{%0,%1,%2,%3}, {%4,%5,%6,%7}, {%8,%9}, {%0,%1,%2,%3};" \
        : "+f"((d)[0]), "+f"((d)[1]), "+f"((d)[2]), "+f"((d)[3]) \
        : "r"((a)[0]), "r"((a)[1]), "r"((a)[2]), "r"((a)[3]), "r"(b0), "r"(b1))

// ---------------------------------------------------------------------------
// FP16 mma.sync GEMM (reverted to round-12 config: best measured, 335us/73.4%).
// 128x128 CTA tile, BK=64 (128B rows, XOR swizzle c^(r&7)), 3-stage cp.async
// (96KB, 2 CTAs/SM), 8 warps (warp tile 64x32), m16n8k16 via ldmatrix.x4.
// MODE 0: f32 C[m*N+n]; MODE 1: fp16 scatter (b,h,t,d) 32 heads; MODE 2: 8.
// ---------------------------------------------------------------------------
#define STAGE_BYTES (128*128)            // 128 rows * 128B (64 fp16)
#define GEMM_SMEM   (3*2*STAGE_BYTES)    // 96 KB

template<int MODE>
__global__ __launch_bounds__(256, 2)
void gemm_f16(const __half* __restrict__ A, const __half* __restrict__ Bw,
              void* __restrict__ Cv, int N, int K)
{
    extern __shared__ __align__(128) uint8_t sm[];
    const uint32_t sbase = (uint32_t)__cvta_generic_to_shared(sm);
    const uint32_t aB0 = sbase;
    const uint32_t bB0 = sbase + 3*STAGE_BYTES;

    const int tid  = threadIdx.x;
    const int w    = tid >> 5;
    const int lane = tid & 31;
    const int wm   = (w & 1) * 64;
    const int wn   = (w >> 1) * 32;
    const int mBase = blockIdx.y << 7;
    const int nBase = blockIdx.x << 7;
    const __half* Ag = A  + (size_t)mBase * K;
    const __half* Bg = Bw + (size_t)nBase * K;

    const int ar  = wm + ((lane >> 3) & 1) * 8 + (lane & 7);
    const int ahi = lane >> 4;
    const int br  = wn + ((lane >> 4) & 1) * 8 + (lane & 7);
    const int bhi = (lane >> 3) & 1;
    const int asw = ar & 7;
    const int bsw = br & 7;

    float acc[4][4][4];
#pragma unroll
    for (int i = 0; i < 4; i++)
#pragma unroll
        for (int j = 0; j < 4; j++)
#pragma unroll
            for (int r = 0; r < 4; r++) acc[i][j][r] = 0.f;

    auto issue = [&](int kt) {
        const int st = kt - (kt/3)*3;
        const int k0 = kt << 6;
        const uint32_t aS = aB0 + st*STAGE_BYTES;
        const uint32_t bS = bB0 + st*STAGE_BYTES;
#pragma unroll
        for (int i = 0; i < 4; i++) {
            int slot = tid + (i << 8);
            int r = slot >> 3;
            int c = slot & 7;
            uint32_t dst = (uint32_t)(r*128 + ((c ^ (r & 7)) << 4));
            cpasync16s(aS + dst, Ag + (size_t)r * K + k0 + c*8);
            cpasync16s(bS + dst, Bg + (size_t)r * K + k0 + c*8);
        }
    };

    const int kTiles = K >> 6;
    issue(0); CP_COMMIT();
    issue(1); CP_COMMIT();

    for (int kt = 0; kt < kTiles; kt++) {
        CP_WAIT(1);
        __syncthreads();
        if (kt + 2 < kTiles) issue(kt + 2);
        CP_COMMIT();

        const int st = kt - (kt/3)*3;
        const uint32_t aS = aB0 + st*STAGE_BYTES;
        const uint32_t bS = bB0 + st*STAGE_BYTES;

#pragma unroll
        for (int h = 0; h < 4; h++) {
            uint32_t a[4][4], b[2][4];
#pragma unroll
            for (int mt = 0; mt < 4; mt++) {
                uint32_t ad = aS + (uint32_t)((ar + mt*16)*128
                              + (((2*h + ahi) ^ asw) << 4));
                LDMX4(a[mt][0], a[mt][1], a[mt][2], a[mt][3], ad);
            }
#pragma unroll
            for (int p = 0; p < 2; p++) {
                uint32_t bd = bS + (uint32_t)((br + p*16)*128
                              + (((2*h + bhi) ^ bsw) << 4));
                LDMX4(b[p][0], b[p][1], b[p][2], b[p][3], bd);
            }
#pragma unroll
            for (int mt = 0; mt < 4; mt++) {
                MMA16(acc[mt][0], a[mt], b[0][0], b[0][1]);
                MMA16(acc[mt][1], a[mt], b[0][2], b[0][3]);
                MMA16(acc[mt][2], a[mt], b[1][0], b[1][1]);
                MMA16(acc[mt][3], a[mt], b[1][2], b[1][3]);
            }
        }
    }

    const int g = lane >> 2, t = lane & 3;
#pragma unroll
    for (int mt = 0; mt < 4; mt++) {
#pragma unroll
        for (int nt = 0; nt < 4; nt++) {
            int m = mBase + wm + mt*16 + g;
            int n = nBase + wn + nt*8 + 2*t;
#pragma unroll
            for (int half = 0; half < 2; half++) {
                int mm = m + half*8;
                float v0 = half ? acc[mt][nt][2] : acc[mt][nt][0];
                float v1 = half ? acc[mt][nt][3] : acc[mt][nt][1];
                if (MODE == 0) {
                    float* C = (float*)Cv;
                    *(float2*)&C[(size_t)mm * N + n] = make_float2(v0, v1);
                } else {
                    __half* C = (__half*)Cv;
                    int bb = mm >> 10, tk = mm & 1023;
                    int h2 = n >> 7, d = n & 127;
                    int heads = (MODE == 1) ? NH : NKV;
                    __half2 hv = __floats2half2_rn(v0, v1);
                    *(uint32_t*)&C[(((size_t)(bb*heads + h2))*SEQ + tk)*HD + d] = h2_as_u32(hv);
                }
            }
        }
    }
}

// ---------------------------------------------------------------------------
// f32 -> fp16 conversion pre-pass
// ---------------------------------------------------------------------------
__global__ void to_half_kernel(__half* __restrict__ dst, const float* __restrict__ src, int n8)
{
    int i = blockIdx.x * blockDim.x + threadIdx.x;
    if (i < n8) {
        float4 v0 = ((const float4*)src)[2*i];
        float4 v1 = ((const float4*)src)[2*i + 1];
        uint4 o;
        o.x = h2_as_u32(__floats2half2_rn(v0.x, v0.y));
        o.y = h2_as_u32(__floats2half2_rn(v0.z, v0.w));
        o.z = h2_as_u32(__floats2half2_rn(v1.x, v1.y));
        o.w = h2_as_u32(__floats2half2_rn(v1.z, v1.w));
        ((uint4*)dst)[i] = o;
    }
}

// ---------------------------------------------------------------------------
// Tensor-core flash attention (fp16 in, f32 softmax/accum, fp16 out).
// Block: 128 q-rows of one (b,h); 8 warps, 16 rows each. K/V tiles of 64
// keys. CHANGED vs r12: 2-stage KV pipeline (96.25KB smem -> 2 CTAs/SM,
// 16 warps) instead of 3-stage @ 1 CTA/SM. Prefetch depth 1.
// Mask: kpos <= qpos+1 AND id[kpos]!=0; kvh = h%8.
// ---------------------------------------------------------------------------
#define ATTN_SMEM (32768 + 2*16384 + 2*16384 + 256)   // 98560 B

__global__ __launch_bounds__(256, 2)
void attn_f16(const int* __restrict__ ids)
{
    extern __shared__ __align__(128) uint8_t smraw[];
    const uint32_t sb = (uint32_t)__cvta_generic_to_shared(smraw);
    const uint32_t Qs = sb;
    const uint32_t Ks = sb + 32768;
    const uint32_t Vs = sb + 32768 + 2*16384;
    float* padb = (float*)(smraw + 32768 + 4*16384);

    const int qt = blockIdx.x, h = blockIdx.y, b = blockIdx.z;
    const int qb  = qt << 7;
    const int kvh = h & 7;
    const int tid = threadIdx.x, w = tid >> 5, lane = tid & 31;
    const int g = lane >> 2, t4 = lane & 3;

    const __half* Qg = g_qh + ((size_t)((b*NH  + h  )*SEQ) + qb) * HD;
    const __half* Kg = g_kh + ((size_t)((b*NKV + kvh)*SEQ)) * HD;
    const __half* Vg = g_vh + ((size_t)((b*NKV + kvh)*SEQ)) * HD;

#pragma unroll
    for (int i = 0; i < 8; i++) {
        int slot = tid + (i << 8);
        int r = slot >> 4, c = slot & 15;
        cpasync16s(Qs + r*256 + ((c ^ (r & 7)) << 4), Qg + (size_t)r*HD + c*8);
    }
    CP_COMMIT();

    const int limit = min(SEQ, qb + 129);
    const int nT = (limit + 63) >> 6;

    auto issueKV = [&](int tt) {
        int st = tt & 1; int k0 = tt << 6;
#pragma unroll
        for (int i = 0; i < 4; i++) {
            int slot = tid + (i << 8);
            int r = slot >> 4, c = slot & 15;
            uint32_t off = (uint32_t)(r*256 + ((c ^ (r & 7)) << 4));
            cpasync16s(Ks + st*16384 + off, Kg + (size_t)(k0 + r)*HD + c*8);
            cpasync16s(Vs + st*16384 + off, Vg + (size_t)(k0 + r)*HD + c*8);
        }
    };

    issueKV(0); CP_COMMIT();

    CP_WAIT(1);                 // Q done (KV0 may be in flight)
    __syncthreads();

    uint32_t qf[8][4];
    const int arow = (w << 4) + (lane & 7) + (((lane >> 3) & 1) << 3);
    const int ahi  = lane >> 4;
#pragma unroll
    for (int kt = 0; kt < 8; kt++) {
        int c = kt*2 + ahi;
        uint32_t ad = Qs + (uint32_t)(arow*256 + ((c ^ (arow & 7)) << 4));
        LDMX4(qf[kt][0], qf[kt][1], qf[kt][2], qf[kt][3], ad);
    }

    const int krow = (lane & 7) + (((lane >> 4) & 1) << 3);
    const int khi  = (lane >> 3) & 1;
    const int vkey = lane & 15;
    const int vhi  = lane >> 4;
    const int row0 = qb + (w << 4) + g;
    const int row1 = row0 + 8;
    const int minrow = qb + (w << 4);

    float m0 = -1e30f, m1 = -1e30f, l0 = 0.f, l1 = 0.f;
    float oacc[16][4];
#pragma unroll
    for (int i = 0; i < 16; i++)
#pragma unroll
        for (int j = 0; j < 4; j++) oacc[i][j] = 0.f;

    for (int tt = 0; tt < nT; tt++) {
        const int st = tt & 1;
        const int k0 = tt << 6;

        __syncthreads();        // prev compute done; stage (tt+1)&1 reusable
        if (tid < 64) padb[tid] = (ids[b*SEQ + k0 + tid] != 0) ? 0.f : -1e30f;
        if (tt + 1 < nT) issueKV(tt + 1);
        CP_COMMIT();
        CP_WAIT(1);             // tile tt ready (only tt+1 outstanding)
        __syncthreads();

        float sacc[8][4];
#pragma unroll
        for (int nt = 0; nt < 8; nt++)
#pragma unroll
            for (int j = 0; j < 4; j++) sacc[nt][j] = 0.f;

        const uint32_t KsS = Ks + st*16384;
#pragma unroll
        for (int np = 0; np < 4; np++) {
#pragma unroll
            for (int kt = 0; kt < 8; kt++) {
                int r = np*16 + krow;
                int c = kt*2 + khi;
                uint32_t bd = KsS + (uint32_t)(r*256 + ((c ^ (r & 7)) << 4));
                uint32_t b0, b1, b2, b3;
                LDMX4(b0, b1, b2, b3, bd);
                MMA16(sacc[np*2],     qf[kt], b0, b1);
                MMA16(sacc[np*2 + 1], qf[kt], b2, b3);
            }
        }

        const bool fullc = (k0 + 63 <= minrow + 1);
        const float sc = 0.08838834764831845f;
        float mx0 = -1e30f, mx1 = -1e30f;
        const float2* pb2 = (const float2*)padb;
#pragma unroll
        for (int nt = 0; nt < 8; nt++) {
            float2 pb = pb2[nt*4 + t4];
            float c0 = sacc[nt][0]*sc + pb.x;
            float c1 = sacc[nt][1]*sc + pb.y;
            float c2 = sacc[nt][2]*sc + pb.x;
            float c3 = sacc[nt][3]*sc + pb.y;
            if (!fullc) {
                int col0 = k0 + nt*8 + 2*t4;
                if (col0     > row0 + 1) c0 = -1e30f;
                if (col0 + 1 > row0 + 1) c1 = -1e30f;
                if (col0     > row1 + 1) c2 = -1e30f;
                if (col0 + 1 > row1 + 1) c3 = -1e30f;
            }
            sacc[nt][0] = c0; sacc[nt][1] = c1; sacc[nt][2] = c2; sacc[nt][3] = c3;
            mx0 = fmaxf(mx0, fmaxf(c0, c1));
            mx1 = fmaxf(mx1, fmaxf(c2, c3));
        }
        mx0 = fmaxf(mx0, __shfl_xor_sync(0xffffffffu, mx0, 1));
        mx0 = fmaxf(mx0, __shfl_xor_sync(0xffffffffu, mx0, 2));
        mx1 = fmaxf(mx1, __shfl_xor_sync(0xffffffffu, mx1, 1));
        mx1 = fmaxf(mx1, __shfl_xor_sync(0xffffffffu, mx1, 2));
        float mn0 = fmaxf(m0, mx0), mn1 = fmaxf(m1, mx1);
        float f0 = __expf(m0 - mn0), f1 = __expf(m1 - mn1);
        m0 = mn0; m1 = mn1;

        float s0 = 0.f, s1 = 0.f;
        uint32_t ph[8][2];
#pragma unroll
        for (int nt = 0; nt < 8; nt++) {
            float p0 = __expf(sacc[nt][0] - mn0);
            float p1 = __expf(sacc[nt][1] - mn0);
            float p2 = __expf(sacc[nt][2] - mn1);
            float p3 = __expf(sacc[nt][3] - mn1);
            s0 += p0 + p1; s1 += p2 + p3;
            ph[nt][0] = h2_as_u32(__floats2half2_rn(p0, p1));
            ph[nt][1] = h2_as_u32(__floats2half2_rn(p2, p3));
        }
        s0 += __shfl_xor_sync(0xffffffffu, s0, 1);
        s0 += __shfl_xor_sync(0xffffffffu, s0, 2);
        s1 += __shfl_xor_sync(0xffffffffu, s1, 1);
        s1 += __shfl_xor_sync(0xffffffffu, s1, 2);
        l0 = l0*f0 + s0; l1 = l1*f1 + s1;

#pragma unroll
        for (int nt = 0; nt < 16; nt++) {
            oacc[nt][0] *= f0; oacc[nt][1] *= f0;
            oacc[nt][2] *= f1; oacc[nt][3] *= f1;
        }

        const uint32_t VsS = Vs + st*16384;
#pragma unroll
        for (int kt2 = 0; kt2 < 4; kt2++) {
            uint32_t a[4] = { ph[kt2*2][0], ph[kt2*2][1],
                              ph[kt2*2 + 1][0], ph[kt2*2 + 1][1] };
#pragma unroll
            for (int u = 0; u < 8; u++) {
                int key = kt2*16 + vkey;
                int c = u*2 + vhi;
                uint32_t vd = VsS + (uint32_t)(key*256 + ((c ^ (key & 7)) << 4));
                uint32_t r0, r1, r2, r3;
                LDMX4T(r0, r1, r2, r3, vd);
                MMA16(oacc[u*2],     a, r0, r1);
                MMA16(oacc[u*2 + 1], a, r2, r3);
            }
        }
    }

    float i0 = 1.f / l0, i1 = 1.f / l1;
    size_t base0 = ((size_t)b*SEQ + row0)*HID + h*HD;
    size_t base1 = ((size_t)b*SEQ + row1)*HID + h*HD;
#pragma unroll
    for (int nt = 0; nt < 16; nt++) {
        int d = nt*8 + 2*t4;
        __half2 v0 = __floats2half2_rn(oacc[nt][0]*i0, oacc[nt][1]*i0);
        __half2 v1 = __floats2half2_rn(oacc[nt][2]*i1, oacc[nt][3]*i1);
        *(uint32_t*)(g_oh + base0 + d) = h2_as_u32(v0);
        *(uint32_t*)(g_oh + base1 + d) = h2_as_u32(v1);
    }
}

// Tail: reference returns (out, start_pos + Tq) — fill any extra output slots.
__global__ void tail_kernel(float* __restrict__ out, const int* __restrict__ sp, int out_size)
{
    int i = MROWS*HID + blockIdx.x*blockDim.x + threadIdx.x;
    if (i < out_size) {
        int s = sp ? *sp : 0;
        out[i] = (float)(s + SEQ);
    }
}

// ---------------------------------------------------------------------------
extern "C" void kernel_launch(void* const* d_in, const int* in_sizes, int n_in,
                              void* d_out, int out_size)
{
    const int*   ids    = (const int*)  d_in[0];
    const float* hidden = (const float*)d_in[1];
    const float* Wq     = (const float*)d_in[2];
    const float* Wk     = (const float*)d_in[3];
    const float* Wv     = (const float*)d_in[4];
    const float* Wo     = (const float*)d_in[5];
    float*       out    = (float*)d_out;

    __half *qh, *kh, *vh, *oh, *hh, *wqh, *wkh, *wvh, *woh;
    cudaGetSymbolAddress((void**)&qh,  g_qh);
    cudaGetSymbolAddress((void**)&kh,  g_kh);
    cudaGetSymbolAddress((void**)&vh,  g_vh);
    cudaGetSymbolAddress((void**)&oh,  g_oh);
    cudaGetSymbolAddress((void**)&hh,  g_hh);
    cudaGetSymbolAddress((void**)&wqh, g_wqh);
    cudaGetSymbolAddress((void**)&wkh, g_wkh);
    cudaGetSymbolAddress((void**)&wvh, g_wvh);
    cudaGetSymbolAddress((void**)&woh, g_woh);

    cudaFuncSetAttribute(gemm_f16<0>, cudaFuncAttributeMaxDynamicSharedMemorySize, GEMM_SMEM);
    cudaFuncSetAttribute(gemm_f16<1>, cudaFuncAttributeMaxDynamicSharedMemorySize, GEMM_SMEM);
    cudaFuncSetAttribute(gemm_f16<2>, cudaFuncAttributeMaxDynamicSharedMemorySize, GEMM_SMEM);
    cudaFuncSetAttribute(attn_f16,    cudaFuncAttributeMaxDynamicSharedMemorySize, ATTN_SMEM);

    auto conv = [&](__half* d, const float* s, size_t n) {
        int n8 = (int)(n / 8);
        to_half_kernel<<<(n8 + 255)/256, 256>>>(d, s, n8);
    };

    dim3 blk(256);
    conv(hh,  hidden, (size_t)MROWS*HID);                                     // 1
    conv(wqh, Wq,     (size_t)HID*HID);                                       // 2
    conv(wkh, Wk,     (size_t)NKV*HD*HID);                                    // 3
    gemm_f16<1><<<dim3(HID/128,      MROWS/128), blk, GEMM_SMEM>>>(hh, wqh, qh, HID,    HID); // 4 <- profiled
    conv(wvh, Wv,     (size_t)NKV*HD*HID);                                    // 5
    conv(woh, Wo,     (size_t)HID*HID);                                       // 6
    gemm_f16<2><<<dim3((NKV*HD)/128, MROWS/128), blk, GEMM_SMEM>>>(hh, wkh, kh, NKV*HD, HID); // 7
    gemm_f16<2><<<dim3((NKV*HD)/128, MROWS/128), blk, GEMM_SMEM>>>(hh, wvh, vh, NKV*HD, HID); // 8

    attn_f16<<<dim3(SEQ/128, NH, BATCH), blk, ATTN_SMEM>>>(ids);              // 9

    gemm_f16<0><<<dim3(HID/128, MROWS/128), blk, GEMM_SMEM>>>(oh, woh, out, HID, HID); // 10

    if (out_size > MROWS*HID) {
        int rem = out_size - MROWS*HID;
        const int* sp = (n_in > 8) ? (const int*)d_in[8] : nullptr;
        tail_kernel<<<(rem + 127)/128, 128>>>(out, sp, out_size);             // 11
    }
}

// round 16
// speedup vs baseline: 1.1220x; 1.0561x over previous
#include <cuda_runtime.h>
#include <cuda_fp16.h>
#include <cstdint>

#define HID   4096
#define NH    32
#define NKV   8
#define HD    128
#define BATCH 4
#define SEQ   1024
#define MROWS (BATCH*SEQ)   // 4096
#define NQKV  (HID + 2*NKV*HD)   // 5120

// ---------------------------------------------------------------------------
// Scratch (static __device__ — no allocations allowed)
// ---------------------------------------------------------------------------
__device__ __half g_qh  [(size_t)BATCH*NH *SEQ*HD];  // (b,h,t,d) fp16
__device__ __half g_kh  [(size_t)BATCH*NKV*SEQ*HD];  // (b,kvh,t,d)
__device__ __half g_vh  [(size_t)BATCH*NKV*SEQ*HD];
__device__ __half g_oh  [(size_t)MROWS*HID];         // attention out fp16
__device__ __half g_hh  [(size_t)MROWS*HID];         // hidden fp16
__device__ __half g_wqkv[(size_t)NQKV*HID];          // packed Wq|Wk|Wv fp16
__device__ __half g_woh [(size_t)HID*HID];

// ---------------------------------------------------------------------------
__device__ __forceinline__ uint32_t h2_as_u32(__half2 h) {
    uint32_t u; memcpy(&u, &h, 4); return u;
}
__device__ __forceinline__ void cpasync16s(uint32_t s, const void* g) {
    asm volatile("cp.async.cg.shared.global [%0], [%1], 16;" :: "r"(s), "l"(g));
}
#define CP_COMMIT() asm volatile("cp.async.commit_group;")
#define CP_WAIT(n)  asm volatile("cp.async.wait_group %0;" :: "n"(n))

#define LDMX4(r0,r1,r2,r3, addr) \
    asm volatile("ldmatrix.sync.aligned.m8n8.x4.shared.b16 {%0,%1,%2,%3}, [%4];" \
        : "=r"(r0), "=r"(r1), "=r"(r2), "=r"(r3) : "r"(addr))

#define LDMX4T(r0,r1,r2,r3, addr) \
    asm volatile("ldmatrix.sync.aligned.m8n8.x4.trans.shared.b16 {%0,%1,%2,%3}, [%4];" \
        : "=r"(r0), "=r"(r1), "=r"(r2), "=r"(r3) : "r"(addr))

#define MMA16(d, a, b0, b1) \
    asm volatile("mma.sync.aligned.m16n8k16.row.col.f32.f16.f16.f32 " \
        "{%0,%1,%2,%3}, {%4,%5,%6,%7}, {%8,%9}, {%0,%1,%2,%3};" \
        : "+f"((d)[0]), "+f"((d)[1]), "+f"((d)[2]), "+f"((d)[3]) \
        : "r"((a)[0]), "r"((a)[1]), "r"((a)[2]), "r"((a)[3]), "r"(b0), "r"(b1))

// ---------------------------------------------------------------------------
// FP16 mma.sync GEMM (round-12 proven config: 128x128 CTA, BK=64, 3-stage
// cp.async, 96KB smem, 2 CTAs/SM, 8 warps @ 64x32, m16n8k16).
// MODE 0: f32 C[m*N+n].
// MODE 3: fused QKV epilogue — n<4096 -> g_qh (32 heads), n<4608 -> g_kh,
//         else g_vh (8 heads each). Region boundaries are CTA-aligned.
// ---------------------------------------------------------------------------
#define STAGE_BYTES (128*128)            // 128 rows * 128B (64 fp16)
#define GEMM_SMEM   (3*2*STAGE_BYTES)    // 96 KB

template<int MODE>
__global__ __launch_bounds__(256, 2)
void gemm_f16(const __half* __restrict__ A, const __half* __restrict__ Bw,
              void* __restrict__ Cv, int N, int K)
{
    extern __shared__ __align__(128) uint8_t sm[];
    const uint32_t sbase = (uint32_t)__cvta_generic_to_shared(sm);
    const uint32_t aB0 = sbase;
    const uint32_t bB0 = sbase + 3*STAGE_BYTES;

    const int tid  = threadIdx.x;
    const int w    = tid >> 5;
    const int lane = tid & 31;
    const int wm   = (w & 1) * 64;
    const int wn   = (w >> 1) * 32;
    const int mBase = blockIdx.y << 7;
    const int nBase = blockIdx.x << 7;
    const __half* Ag = A  + (size_t)mBase * K;
    const __half* Bg = Bw + (size_t)nBase * K;

    const int ar  = wm + ((lane >> 3) & 1) * 8 + (lane & 7);
    const int ahi = lane >> 4;
    const int br  = wn + ((lane >> 4) & 1) * 8 + (lane & 7);
    const int bhi = (lane >> 3) & 1;
    const int asw = ar & 7;
    const int bsw = br & 7;

    float acc[4][4][4];
#pragma unroll
    for (int i = 0; i < 4; i++)
#pragma unroll
        for (int j = 0; j < 4; j++)
#pragma unroll
            for (int r = 0; r < 4; r++) acc[i][j][r] = 0.f;

    auto issue = [&](int kt) {
        const int st = kt - (kt/3)*3;
        const int k0 = kt << 6;
        const uint32_t aS = aB0 + st*STAGE_BYTES;
        const uint32_t bS = bB0 + st*STAGE_BYTES;
#pragma unroll
        for (int i = 0; i < 4; i++) {
            int slot = tid + (i << 8);
            int r = slot >> 3;
            int c = slot & 7;
            uint32_t dst = (uint32_t)(r*128 + ((c ^ (r & 7)) << 4));
            cpasync16s(aS + dst, Ag + (size_t)r * K + k0 + c*8);
            cpasync16s(bS + dst, Bg + (size_t)r * K + k0 + c*8);
        }
    };

    const int kTiles = K >> 6;
    issue(0); CP_COMMIT();
    issue(1); CP_COMMIT();

    for (int kt = 0; kt < kTiles; kt++) {
        CP_WAIT(1);
        __syncthreads();
        if (kt + 2 < kTiles) issue(kt + 2);
        CP_COMMIT();

        const int st = kt - (kt/3)*3;
        const uint32_t aS = aB0 + st*STAGE_BYTES;
        const uint32_t bS = bB0 + st*STAGE_BYTES;

#pragma unroll
        for (int h = 0; h < 4; h++) {
            uint32_t a[4][4], b[2][4];
#pragma unroll
            for (int mt = 0; mt < 4; mt++) {
                uint32_t ad = aS + (uint32_t)((ar + mt*16)*128
                              + (((2*h + ahi) ^ asw) << 4));
                LDMX4(a[mt][0], a[mt][1], a[mt][2], a[mt][3], ad);
            }
#pragma unroll
            for (int p = 0; p < 2; p++) {
                uint32_t bd = bS + (uint32_t)((br + p*16)*128
                              + (((2*h + bhi) ^ bsw) << 4));
                LDMX4(b[p][0], b[p][1], b[p][2], b[p][3], bd);
            }
#pragma unroll
            for (int mt = 0; mt < 4; mt++) {
                MMA16(acc[mt][0], a[mt], b[0][0], b[0][1]);
                MMA16(acc[mt][1], a[mt], b[0][2], b[0][3]);
                MMA16(acc[mt][2], a[mt], b[1][0], b[1][1]);
                MMA16(acc[mt][3], a[mt], b[1][2], b[1][3]);
            }
        }
    }

    const int g = lane >> 2, t = lane & 3;
#pragma unroll
    for (int mt = 0; mt < 4; mt++) {
#pragma unroll
        for (int nt = 0; nt < 4; nt++) {
            int m = mBase + wm + mt*16 + g;
            int n = nBase + wn + nt*8 + 2*t;
#pragma unroll
            for (int half = 0; half < 2; half++) {
                int mm = m + half*8;
                float v0 = half ? acc[mt][nt][2] : acc[mt][nt][0];
                float v1 = half ? acc[mt][nt][3] : acc[mt][nt][1];
                if (MODE == 0) {
                    float* C = (float*)Cv;
                    *(float2*)&C[(size_t)mm * N + n] = make_float2(v0, v1);
                } else {   // MODE 3: fused QKV scatter
                    int bb = mm >> 10, tk = mm & 1023;
                    uint32_t u = h2_as_u32(__floats2half2_rn(v0, v1));
                    if (n < HID) {
                        int h2 = n >> 7, d = n & 127;
                        *(uint32_t*)&g_qh[(((size_t)(bb*NH + h2))*SEQ + tk)*HD + d] = u;
                    } else if (n < HID + NKV*HD) {
                        int nn = n - HID; int h2 = nn >> 7, d = nn & 127;
                        *(uint32_t*)&g_kh[(((size_t)(bb*NKV + h2))*SEQ + tk)*HD + d] = u;
                    } else {
                        int nn = n - HID - NKV*HD; int h2 = nn >> 7, d = nn & 127;
                        *(uint32_t*)&g_vh[(((size_t)(bb*NKV + h2))*SEQ + tk)*HD + d] = u;
                    }
                }
            }
        }
    }
}

// ---------------------------------------------------------------------------
// f32 -> fp16 conversion pre-passes
// ---------------------------------------------------------------------------
__global__ void to_half_kernel(__half* __restrict__ dst, const float* __restrict__ src, int n8)
{
    int i = blockIdx.x * blockDim.x + threadIdx.x;
    if (i < n8) {
        float4 v0 = ((const float4*)src)[2*i];
        float4 v1 = ((const float4*)src)[2*i + 1];
        uint4 o;
        o.x = h2_as_u32(__floats2half2_rn(v0.x, v0.y));
        o.y = h2_as_u32(__floats2half2_rn(v0.z, v0.w));
        o.z = h2_as_u32(__floats2half2_rn(v1.x, v1.y));
        o.w = h2_as_u32(__floats2half2_rn(v1.z, v1.w));
        ((uint4*)dst)[i] = o;
    }
}

// Convert Wq, Wk, Wv into the packed g_wqkv buffer in one launch.
__global__ void to_half3_kernel(const float* __restrict__ wq,
                                const float* __restrict__ wk,
                                const float* __restrict__ wv)
{
    const int n8q = (HID*HID)/8, n8k = (NKV*HD*HID)/8;
    int i = blockIdx.x * blockDim.x + threadIdx.x;
    const float* src; __half* dst; int j;
    if (i < n8q)               { src = wq; dst = g_wqkv;                       j = i; }
    else if (i < n8q + n8k)    { src = wk; dst = g_wqkv + (size_t)HID*HID;     j = i - n8q; }
    else if (i < n8q + 2*n8k)  { src = wv; dst = g_wqkv + (size_t)(HID+NKV*HD)*HID; j = i - n8q - n8k; }
    else return;
    float4 v0 = ((const float4*)src)[2*j];
    float4 v1 = ((const float4*)src)[2*j + 1];
    uint4 o;
    o.x = h2_as_u32(__floats2half2_rn(v0.x, v0.y));
    o.y = h2_as_u32(__floats2half2_rn(v0.z, v0.w));
    o.z = h2_as_u32(__floats2half2_rn(v1.x, v1.y));
    o.w = h2_as_u32(__floats2half2_rn(v1.z, v1.w));
    ((uint4*)dst)[j] = o;
}

// ---------------------------------------------------------------------------
// Tensor-core flash attention (round-12 proven config: 3-stage KV pipeline,
// 1 CTA/SM). Block: 128 q-rows of one (b,h); 8 warps, 16 rows each.
// Mask: kpos <= qpos+1 AND id[kpos]!=0; kvh = h%8.
// ---------------------------------------------------------------------------
#define ATTN_SMEM (32768 + 3*16384 + 3*16384 + 256)

__global__ __launch_bounds__(256, 1)
void attn_f16(const int* __restrict__ ids)
{
    extern __shared__ __align__(128) uint8_t smraw[];
    const uint32_t sb = (uint32_t)__cvta_generic_to_shared(smraw);
    const uint32_t Qs = sb;
    const uint32_t Ks = sb + 32768;
    const uint32_t Vs = sb + 32768 + 3*16384;
    float* padb = (float*)(smraw + 32768 + 6*16384);

    const int qt = blockIdx.x, h = blockIdx.y, b = blockIdx.z;
    const int qb  = qt << 7;
    const int kvh = h & 7;
    const int tid = threadIdx.x, w = tid >> 5, lane = tid & 31;
    const int g = lane >> 2, t4 = lane & 3;

    const __half* Qg = g_qh + ((size_t)((b*NH  + h  )*SEQ) + qb) * HD;
    const __half* Kg = g_kh + ((size_t)((b*NKV + kvh)*SEQ)) * HD;
    const __half* Vg = g_vh + ((size_t)((b*NKV + kvh)*SEQ)) * HD;

#pragma unroll
    for (int i = 0; i < 8; i++) {
        int slot = tid + (i << 8);
        int r = slot >> 4, c = slot & 15;
        cpasync16s(Qs + r*256 + ((c ^ (r & 7)) << 4), Qg + (size_t)r*HD + c*8);
    }
    CP_COMMIT();

    const int limit = min(SEQ, qb + 129);
    const int nT = (limit + 63) >> 6;

    auto issueKV = [&](int tt) {
        int st = tt % 3; int k0 = tt << 6;
#pragma unroll
        for (int i = 0; i < 4; i++) {
            int slot = tid + (i << 8);
            int r = slot >> 4, c = slot & 15;
            uint32_t off = (uint32_t)(r*256 + ((c ^ (r & 7)) << 4));
            cpasync16s(Ks + st*16384 + off, Kg + (size_t)(k0 + r)*HD + c*8);
            cpasync16s(Vs + st*16384 + off, Vg + (size_t)(k0 + r)*HD + c*8);
        }
    };

    issueKV(0); CP_COMMIT();
    if (nT > 1) issueKV(1);
    CP_COMMIT();

    CP_WAIT(2);
    __syncthreads();

    uint32_t qf[8][4];
    const int arow = (w << 4) + (lane & 7) + (((lane >> 3) & 1) << 3);
    const int ahi  = lane >> 4;
#pragma unroll
    for (int kt = 0; kt < 8; kt++) {
        int c = kt*2 + ahi;
        uint32_t ad = Qs + (uint32_t)(arow*256 + ((c ^ (arow & 7)) << 4));
        LDMX4(qf[kt][0], qf[kt][1], qf[kt][2], qf[kt][3], ad);
    }

    const int krow = (lane & 7) + (((lane >> 4) & 1) << 3);
    const int khi  = (lane >> 3) & 1;
    const int vkey = lane & 15;
    const int vhi  = lane >> 4;
    const int row0 = qb + (w << 4) + g;
    const int row1 = row0 + 8;
    const int minrow = qb + (w << 4);

    float m0 = -1e30f, m1 = -1e30f, l0 = 0.f, l1 = 0.f;
    float oacc[16][4];
#pragma unroll
    for (int i = 0; i < 16; i++)
#pragma unroll
        for (int j = 0; j < 4; j++) oacc[i][j] = 0.f;

    for (int tt = 0; tt < nT; tt++) {
        const int st = tt % 3;
        const int k0 = tt << 6;

        __syncthreads();
        if (tid < 64) padb[tid] = (ids[b*SEQ + k0 + tid] != 0) ? 0.f : -1e30f;
        if (tt + 2 < nT) issueKV(tt + 2);
        CP_COMMIT();
        CP_WAIT(2);
        __syncthreads();

        float sacc[8][4];
#pragma unroll
        for (int nt = 0; nt < 8; nt++)
#pragma unroll
            for (int j = 0; j < 4; j++) sacc[nt][j] = 0.f;

        const uint32_t KsS = Ks + st*16384;
#pragma unroll
        for (int np = 0; np < 4; np++) {
#pragma unroll
            for (int kt = 0; kt < 8; kt++) {
                int r = np*16 + krow;
                int c = kt*2 + khi;
                uint32_t bd = KsS + (uint32_t)(r*256 + ((c ^ (r & 7)) << 4));
                uint32_t b0, b1, b2, b3;
                LDMX4(b0, b1, b2, b3, bd);
                MMA16(sacc[np*2],     qf[kt], b0, b1);
                MMA16(sacc[np*2 + 1], qf[kt], b2, b3);
            }
        }

        const bool fullc = (k0 + 63 <= minrow + 1);
        const float sc = 0.08838834764831845f;
        float mx0 = -1e30f, mx1 = -1e30f;
        const float2* pb2 = (const float2*)padb;
#pragma unroll
        for (int nt = 0; nt < 8; nt++) {
            float2 pb = pb2[nt*4 + t4];
            float c0 = sacc[nt][0]*sc + pb.x;
            float c1 = sacc[nt][1]*sc + pb.y;
            float c2 = sacc[nt][2]*sc + pb.x;
            float c3 = sacc[nt][3]*sc + pb.y;
            if (!fullc) {
                int col0 = k0 + nt*8 + 2*t4;
                if (col0     > row0 + 1) c0 = -1e30f;
                if (col0 + 1 > row0 + 1) c1 = -1e30f;
                if (col0     > row1 + 1) c2 = -1e30f;
                if (col0 + 1 > row1 + 1) c3 = -1e30f;
            }
            sacc[nt][0] = c0; sacc[nt][1] = c1; sacc[nt][2] = c2; sacc[nt][3] = c3;
            mx0 = fmaxf(mx0, fmaxf(c0, c1));
            mx1 = fmaxf(mx1, fmaxf(c2, c3));
        }
        mx0 = fmaxf(mx0, __shfl_xor_sync(0xffffffffu, mx0, 1));
        mx0 = fmaxf(mx0, __shfl_xor_sync(0xffffffffu, mx0, 2));
        mx1 = fmaxf(mx1, __shfl_xor_sync(0xffffffffu, mx1, 1));
        mx1 = fmaxf(mx1, __shfl_xor_sync(0xffffffffu, mx1, 2));
        float mn0 = fmaxf(m0, mx0), mn1 = fmaxf(m1, mx1);
        float f0 = __expf(m0 - mn0), f1 = __expf(m1 - mn1);
        m0 = mn0; m1 = mn1;

        float s0 = 0.f, s1 = 0.f;
        uint32_t ph[8][2];
#pragma unroll
        for (int nt = 0; nt < 8; nt++) {
            float p0 = __expf(sacc[nt][0] - mn0);
            float p1 = __expf(sacc[nt][1] - mn0);
            float p2 = __expf(sacc[nt][2] - mn1);
            float p3 = __expf(sacc[nt][3] - mn1);
            s0 += p0 + p1; s1 += p2 + p3;
            ph[nt][0] = h2_as_u32(__floats2half2_rn(p0, p1));
            ph[nt][1] = h2_as_u32(__floats2half2_rn(p2, p3));
        }
        s0 += __shfl_xor_sync(0xffffffffu, s0, 1);
        s0 += __shfl_xor_sync(0xffffffffu, s0, 2);
        s1 += __shfl_xor_sync(0xffffffffu, s1, 1);
        s1 += __shfl_xor_sync(0xffffffffu, s1, 2);
        l0 = l0*f0 + s0; l1 = l1*f1 + s1;

#pragma unroll
        for (int nt = 0; nt < 16; nt++) {
            oacc[nt][0] *= f0; oacc[nt][1] *= f0;
            oacc[nt][2] *= f1; oacc[nt][3] *= f1;
        }

        const uint32_t VsS = Vs + st*16384;
#pragma unroll
        for (int kt2 = 0; kt2 < 4; kt2++) {
            uint32_t a[4] = { ph[kt2*2][0], ph[kt2*2][1],
                              ph[kt2*2 + 1][0], ph[kt2*2 + 1][1] };
#pragma unroll
            for (int u = 0; u < 8; u++) {
                int key = kt2*16 + vkey;
                int c = u*2 + vhi;
                uint32_t vd = VsS + (uint32_t)(key*256 + ((c ^ (key & 7)) << 4));
                uint32_t r0, r1, r2, r3;
                LDMX4T(r0, r1, r2, r3, vd);
                MMA16(oacc[u*2],     a, r0, r1);
                MMA16(oacc[u*2 + 1], a, r2, r3);
            }
        }
    }

    float i0 = 1.f / l0, i1 = 1.f / l1;
    size_t base0 = ((size_t)b*SEQ + row0)*HID + h*HD;
    size_t base1 = ((size_t)b*SEQ + row1)*HID + h*HD;
#pragma unroll
    for (int nt = 0; nt < 16; nt++) {
        int d = nt*8 + 2*t4;
        __half2 v0 = __floats2half2_rn(oacc[nt][0]*i0, oacc[nt][1]*i0);
        __half2 v1 = __floats2half2_rn(oacc[nt][2]*i1, oacc[nt][3]*i1);
        *(uint32_t*)(g_oh + base0 + d) = h2_as_u32(v0);
        *(uint32_t*)(g_oh + base1 + d) = h2_as_u32(v1);
    }
}

// Tail: reference returns (out, start_pos + Tq) — fill any extra output slots.
__global__ void tail_kernel(float* __restrict__ out, const int* __restrict__ sp, int out_size)
{
    int i = MROWS*HID + blockIdx.x*blockDim.x + threadIdx.x;
    if (i < out_size) {
        int s = sp ? *sp : 0;
        out[i] = (float)(s + SEQ);
    }
}

// ---------------------------------------------------------------------------
extern "C" void kernel_launch(void* const* d_in, const int* in_sizes, int n_in,
                              void* d_out, int out_size)
{
    const int*   ids    = (const int*)  d_in[0];
    const float* hidden = (const float*)d_in[1];
    const float* Wq     = (const float*)d_in[2];
    const float* Wk     = (const float*)d_in[3];
    const float* Wv     = (const float*)d_in[4];
    const float* Wo     = (const float*)d_in[5];
    float*       out    = (float*)d_out;

    __half *oh, *hh, *wqkv, *woh;
    cudaGetSymbolAddress((void**)&oh,   g_oh);
    cudaGetSymbolAddress((void**)&hh,   g_hh);
    cudaGetSymbolAddress((void**)&wqkv, g_wqkv);
    cudaGetSymbolAddress((void**)&woh,  g_woh);

    cudaFuncSetAttribute(gemm_f16<0>, cudaFuncAttributeMaxDynamicSharedMemorySize, GEMM_SMEM);
    cudaFuncSetAttribute(gemm_f16<3>, cudaFuncAttributeMaxDynamicSharedMemorySize, GEMM_SMEM);
    cudaFuncSetAttribute(attn_f16,    cudaFuncAttributeMaxDynamicSharedMemorySize, ATTN_SMEM);

    dim3 blk(256);

    // 1: hidden -> fp16
    {
        int n8 = (MROWS*HID)/8;
        to_half_kernel<<<(n8 + 255)/256, 256>>>(hh, hidden, n8);
    }
    // 2: Wq|Wk|Wv -> packed fp16 buffer (one launch)
    {
        int n8 = (HID*HID + 2*NKV*HD*HID)/8;
        to_half3_kernel<<<(n8 + 255)/256, 256>>>(Wq, Wk, Wv);
    }
    // 3: Wo -> fp16
    {
        int n8 = (HID*HID)/8;
        to_half_kernel<<<(n8 + 255)/256, 256>>>(woh, Wo, n8);
    }
    // 4: fused QKV GEMM  (profiled — launch #4)
    gemm_f16<3><<<dim3(NQKV/128, MROWS/128), blk, GEMM_SMEM>>>(hh, wqkv, nullptr, NQKV, HID);
    // 5: attention
    attn_f16<<<dim3(SEQ/128, NH, BATCH), blk, ATTN_SMEM>>>(ids);
    // 6: output projection
    gemm_f16<0><<<dim3(HID/128, MROWS/128), blk, GEMM_SMEM>>>(oh, woh, out, HID, HID);

    if (out_size > MROWS*HID) {
        int rem = out_size - MROWS*HID;
        const int* sp = (n_in > 8) ? (const int*)d_in[8] : nullptr;
        tail_kernel<<<(rem + 127)/128, 128>>>(out, sp, out_size);
    }
}